// round 12
// baseline (speedup 1.0000x reference)
#include <cuda_runtime.h>
#include <math.h>

#define BPSM  5              // blocks per SM (single-buffered body fits <64 regs)
#define GRID  (148 * BPSM)   // one wave
#define NTHR  256
#define NWARP (NTHR / 32)
#define PFD   6              // prefetch distance in 256-row iterations

#define K2F   43.28085122666891f    // 30*log2(e)
#define C0F   21.640425613334455f   // 15*log2(e)
#define LN2D  0.6931471805599453

__device__ __forceinline__ float ex2f(float x){ float r; asm("ex2.approx.ftz.f32 %0, %1;" : "=f"(r) : "f"(x)); return r; }
__device__ __forceinline__ float lg2f(float x){ float r; asm("lg2.approx.ftz.f32 %0, %1;" : "=f"(r) : "f"(x)); return r; }

struct Chain { int f0, l0, S0, f1, l1, S1; };

__device__ __forceinline__ Chain chain_combine(const Chain& a, const Chain& b) {
    Chain r;
    r.S0 = a.S0 + b.S0 + a.l0 * b.f0;
    r.S1 = a.S1 + b.S1 + a.l1 * b.f1;
    r.f0 = a.f0 ? a.f0 : b.f0;
    r.f1 = a.f1 ? a.f1 : b.f1;
    r.l0 = b.l0 ? b.l0 : a.l0;
    r.l1 = b.l1 ? b.l1 : a.l1;
    return r;
}

// Ballot+shfl ordered combine of 32 lane-chains (one class) in O(1).
__device__ __forceinline__ void warp_chain(int f, int l, int S, int lane,
                                           int& Fw, int& Lw, int& Sw)
{
    unsigned m     = __ballot_sync(0xffffffffu, f != 0);
    unsigned below = m & ((1u << lane) - 1u);
    int prev_l = __shfl_sync(0xffffffffu, l, below ? (31 - __clz(below)) : 0);
    int term   = (f != 0 && below) ? prev_l * f : 0;
    Sw = __reduce_add_sync(0xffffffffu, S + term);
    int fsrc = m ? (__ffs(m) - 1) : 0;
    int lsrc = m ? (31 - __clz(m)) : 0;
    Fw = __shfl_sync(0xffffffffu, f, fsrc);
    Lw = __shfl_sync(0xffffffffu, l, lsrc);
    if (!m) { Fw = 0; Lw = 0; }
}

__device__ float    g_l[GRID];
__device__ float    g_f[GRID];
__device__ int      g_n1[GRID];
__device__ int      g_c[GRID][6];
__device__ unsigned g_count = 0;   // reset by last block each run (replay-safe)

// Per-row work, log2 domain, weights folded into the accumulators.
__device__ __forceinline__ void row_op(float x0, float x1, int t, float c1,
                                       float& lsum, float& fsum,
                                       int& l0, int& l1, int& S0, int& S1,
                                       int& f0, int& f1)
{
    float d = x0 - x1;
    bool  P = (t != 0);

    float a2 = P ? fmaf(K2F, d, c1) : fmaf(-K2F, d, C0F);
    float nl = lg2f(1.0f + ex2f(a2));
    if (P) lsum = fmaf(0.85f, nl, lsum); else lsum = fmaf(0.15f, nl, lsum);

    float one = 1.0f - x1;
    float la  = P ? x1 : one;
    float om  = P ? one : x1;
    float lg  = lg2f(la + 1e-9f);
    float sl  = (om * om) * lg;
    if (P) fsum = fmaf(0.85f, sl, fsum); else fsum = fmaf(0.15f, sl, fsum);

    int s = (__float_as_int(d) >> 31) | 1;     // d<0 -> -1 else +1
    if (P) { S1 += l1 * s; f1 = f1 ? f1 : s; l1 = s; }
    else   { S0 += l0 * s; f0 = f0 ? f0 : s; l0 = s; }
}

__global__ void __launch_bounds__(NTHR, BPSM) fused_loss(
    const float* __restrict__ x, const int* __restrict__ tg,
    float* __restrict__ out, int B, int rpw, float c1)
{
    const int lane = threadIdx.x & 31;
    const int warp = threadIdx.x >> 5;
    const int tid  = threadIdx.x;

    long long wbase = ((long long)blockIdx.x * NWARP + warp) * (long long)rpw;

    float lsum = 0.f, fsum = 0.f;
    int n1 = 0;
    Chain wacc = {0, 0, 0, 0, 0, 0};

    const int iters = rpw >> 8;                 // 256 rows per warp-iteration

    if (wbase + (long long)rpw <= (long long)B) {
        // -------- full path: single buffer + deep L2 prefetch --------
        const float4* px = (const float4*)x  + ((wbase + lane * 8) >> 1);
        const int4*   pt = (const int4*)tg + ((wbase + lane * 8) >> 2);
        for (int j = 0; j < iters; ++j) {
            asm volatile("prefetch.global.L2 [%0];" :: "l"(px + PFD * 128));
            asm volatile("prefetch.global.L2 [%0];" :: "l"(pt + PFD * 64));
            float4 xa = __ldcs(px + 0);
            float4 xb = __ldcs(px + 1);
            float4 xc = __ldcs(px + 2);
            float4 xd = __ldcs(px + 3);
            int4   ta = __ldcs(pt + 0);
            int4   tb = __ldcs(pt + 1);
            px += 128;  pt += 64;               // 256 rows forward
            int l0 = 0, l1 = 0, S0 = 0, S1 = 0, f0 = 0, f1 = 0;
            row_op(xa.x, xa.y, ta.x, c1, lsum, fsum, l0, l1, S0, S1, f0, f1);
            row_op(xa.z, xa.w, ta.y, c1, lsum, fsum, l0, l1, S0, S1, f0, f1);
            row_op(xb.x, xb.y, ta.z, c1, lsum, fsum, l0, l1, S0, S1, f0, f1);
            row_op(xb.z, xb.w, ta.w, c1, lsum, fsum, l0, l1, S0, S1, f0, f1);
            row_op(xc.x, xc.y, tb.x, c1, lsum, fsum, l0, l1, S0, S1, f0, f1);
            row_op(xc.z, xc.w, tb.y, c1, lsum, fsum, l0, l1, S0, S1, f0, f1);
            row_op(xd.x, xd.y, tb.z, c1, lsum, fsum, l0, l1, S0, S1, f0, f1);
            row_op(xd.z, xd.w, tb.w, c1, lsum, fsum, l0, l1, S0, S1, f0, f1);
            n1 += (ta.x + ta.y + ta.z) + (ta.w + tb.x + tb.y) + (tb.z + tb.w);
            int F0, L0, Sw0, F1, L1, Sw1;
            warp_chain(f0, l0, S0, lane, F0, L0, Sw0);
            warp_chain(f1, l1, S1, lane, F1, L1, Sw1);
            wacc.S0 += Sw0 + wacc.l0 * F0;
            wacc.f0  = wacc.f0 ? wacc.f0 : F0;
            wacc.l0  = L0 ? L0 : wacc.l0;
            wacc.S1 += Sw1 + wacc.l1 * F1;
            wacc.f1  = wacc.f1 ? wacc.f1 : F1;
            wacc.l1  = L1 ? L1 : wacc.l1;
        }
    } else if (wbase < (long long)B) {
        // -------- tail path (at most one warp strip crosses B) --------
        for (int j = 0; j < iters; ++j) {
            long long base = wbase + (long long)j * 256;
            if (base >= (long long)B) break;
            long long row0 = base + lane * 8;
            int l0 = 0, l1 = 0, S0 = 0, S1 = 0, f0 = 0, f1 = 0;
            for (int k = 0; k < 8; ++k) {
                long long r = row0 + k;
                if (r < (long long)B) {
                    int t = tg[(int)r];
                    row_op(x[2 * r], x[2 * r + 1], t, c1,
                           lsum, fsum, l0, l1, S0, S1, f0, f1);
                    n1 += t;
                }
            }
            int F0, L0, Sw0, F1, L1, Sw1;
            warp_chain(f0, l0, S0, lane, F0, L0, Sw0);
            warp_chain(f1, l1, S1, lane, F1, L1, Sw1);
            wacc.S0 += Sw0 + wacc.l0 * F0;
            wacc.f0  = wacc.f0 ? wacc.f0 : F0;
            wacc.l0  = L0 ? L0 : wacc.l0;
            wacc.S1 += Sw1 + wacc.l1 * F1;
            wacc.f1  = wacc.f1 ? wacc.f1 : F1;
            wacc.l1  = L1 ? L1 : wacc.l1;
        }
    }

    #pragma unroll
    for (int off = 16; off; off >>= 1) {
        lsum += __shfl_down_sync(0xffffffffu, lsum, off);
        fsum += __shfl_down_sync(0xffffffffu, fsum, off);
    }
    n1 = __reduce_add_sync(0xffffffffu, n1);

    __shared__ Chain smon[NWARP];
    __shared__ float sls[NWARP], sfs[NWARP];
    __shared__ int   sn1[NWARP];
    if (lane == 0) { smon[warp] = wacc; sls[warp] = lsum; sfs[warp] = fsum; sn1[warp] = n1; }
    __syncthreads();
    if (tid == 0) {
        Chain c = smon[0];
        float fl = sls[0], ff = sfs[0];
        int nn = sn1[0];
        for (int w = 1; w < NWARP; ++w) {
            c = chain_combine(c, smon[w]);
            fl += sls[w]; ff += sfs[w]; nn += sn1[w];
        }
        g_l[blockIdx.x]  = fl;
        g_f[blockIdx.x]  = ff;
        g_n1[blockIdx.x] = nn;
        int* m = g_c[blockIdx.x];
        m[0] = c.f0; m[1] = c.l0; m[2] = c.S0;
        m[3] = c.f1; m[4] = c.l1; m[5] = c.S1;
    }

    // ---- last-block final reduction ----
    __shared__ unsigned s_last;
    if (tid == 0) {
        __threadfence();
        unsigned r = atomicAdd(&g_count, 1u);
        s_last = (r == (unsigned)(gridDim.x - 1));
    }
    __syncthreads();
    if (!s_last) return;
    __threadfence();

    const int CH = (GRID + NTHR - 1) / NTHR;
    Chain c = {0, 0, 0, 0, 0, 0};
    double dl = 0.0, df = 0.0;
    long long nn = 0;
    #pragma unroll
    for (int k = 0; k < CH; ++k) {
        int i = tid * CH + k;
        if (i < GRID) {
            const int* m = g_c[i];
            Chain b = {m[0], m[1], m[2], m[3], m[4], m[5]};
            c = chain_combine(c, b);
            dl += (double)g_l[i]; df += (double)g_f[i]; nn += g_n1[i];
        }
    }
    int F0, L0, S0, F1, L1, S1;
    warp_chain(c.f0, c.l0, c.S0, lane, F0, L0, S0);
    warp_chain(c.f1, c.l1, c.S1, lane, F1, L1, S1);
    #pragma unroll
    for (int off = 16; off; off >>= 1) {
        dl += __shfl_down_sync(0xffffffffu, dl, off);
        df += __shfl_down_sync(0xffffffffu, df, off);
        nn += __shfl_down_sync(0xffffffffu, nn, off);
    }

    __shared__ Chain s2mon[NWARP];
    __shared__ double s2l[NWARP], s2f[NWARP];
    __shared__ long long s2n[NWARP];
    if (lane == 0) {
        Chain wc = {F0, L0, S0, F1, L1, S1};
        s2mon[warp] = wc; s2l[warp] = dl; s2f[warp] = df; s2n[warp] = nn;
    }
    __syncthreads();
    if (tid == 0) {
        Chain t = s2mon[0];
        double tl = s2l[0], tf = s2f[0];
        long long tn = s2n[0];
        for (int w = 1; w < NWARP; ++w) {
            t = chain_combine(t, s2mon[w]);
            tl += s2l[w]; tf += s2f[w]; tn += s2n[w];
        }
        long long n1t = tn;
        long long n0t = (long long)B - n1t;
        double W     = 0.15 * (double)n0t + 0.85 * (double)n1t;
        double ldam  = LN2D * tl / W;
        double focal = -LN2D * tf / (double)B;
        double p0 = (n0t > 0) ? (double)t.S0 / (double)n0t : 0.0;
        double p1 = (n1t > 0) ? (double)t.S1 / (double)n1t : 0.0;
        double dp = p0 - p1;
        out[0] = (float)(ldam + focal + dp * dp);
        __threadfence();
        g_count = 0;
    }
}

extern "C" void kernel_launch(void* const* d_in, const int* in_sizes, int n_in,
                              void* d_out, int out_size)
{
    const float* x  = (const float*)d_in[0];
    const int*   tg = (const int*)d_in[1];
    int B = in_sizes[1];

    // rows per warp, multiple of 256 (one warp-iteration)
    int wtot = GRID * NWARP;
    int rpw = (B + wtot - 1) / wtot;
    rpw = (rpw + 255) & ~255;

    // class-1 LDAM margin * 30 * log2(e)
    float c1 = (float)(30.0 * 0.5 * pow(85.0 / 900.0, 0.25) * 1.4426950408889634);

    fused_loss<<<GRID, NTHR>>>(x, tg, (float*)d_out, B, rpw, c1);
}

// round 13
// speedup vs baseline: 1.3356x; 1.3356x over previous
#include <cuda_runtime.h>
#include <math.h>

#define BPSM  3              // blocks per SM -> 84-reg budget, room for double buffer
#define GRID  (148 * BPSM)   // one wave
#define NTHR  256
#define NWARP (NTHR / 32)
#define PFD   6              // prefetch distance in 256-row iterations

#define K2F   43.28085122666891f    // 30*log2(e)
#define C0F   21.640425613334455f   // 15*log2(e)
#define LN2D  0.6931471805599453

__device__ __forceinline__ float ex2f(float x){ float r; asm("ex2.approx.ftz.f32 %0, %1;" : "=f"(r) : "f"(x)); return r; }
__device__ __forceinline__ float lg2f(float x){ float r; asm("lg2.approx.ftz.f32 %0, %1;" : "=f"(r) : "f"(x)); return r; }

struct Chain { int f0, l0, S0, f1, l1, S1; };

__device__ __forceinline__ Chain chain_combine(const Chain& a, const Chain& b) {
    Chain r;
    r.S0 = a.S0 + b.S0 + a.l0 * b.f0;
    r.S1 = a.S1 + b.S1 + a.l1 * b.f1;
    r.f0 = a.f0 ? a.f0 : b.f0;
    r.f1 = a.f1 ? a.f1 : b.f1;
    r.l0 = b.l0 ? b.l0 : a.l0;
    r.l1 = b.l1 ? b.l1 : a.l1;
    return r;
}

// Ballot+shfl ordered combine of 32 lane-chains (one class) in O(1).
__device__ __forceinline__ void warp_chain(int f, int l, int S, int lane,
                                           int& Fw, int& Lw, int& Sw)
{
    unsigned m     = __ballot_sync(0xffffffffu, f != 0);
    unsigned below = m & ((1u << lane) - 1u);
    int prev_l = __shfl_sync(0xffffffffu, l, below ? (31 - __clz(below)) : 0);
    int term   = (f != 0 && below) ? prev_l * f : 0;
    Sw = __reduce_add_sync(0xffffffffu, S + term);
    int fsrc = m ? (__ffs(m) - 1) : 0;
    int lsrc = m ? (31 - __clz(m)) : 0;
    Fw = __shfl_sync(0xffffffffu, f, fsrc);
    Lw = __shfl_sync(0xffffffffu, l, lsrc);
    if (!m) { Fw = 0; Lw = 0; }
}

__device__ float    g_l[GRID];
__device__ float    g_f[GRID];
__device__ int      g_n1[GRID];
__device__ int      g_c[GRID][6];
__device__ unsigned g_count = 0;   // reset by last block each run (replay-safe)

// Per-row work, log2 domain. Shared class-weight w (one SEL) feeds two
// unpredicated FMAs -> fewer dual-emitted predicated instructions.
__device__ __forceinline__ void row_op(float x0, float x1, int t, float c1,
                                       float& lsum, float& fsum,
                                       int& l0, int& l1, int& S0, int& S1,
                                       int& f0, int& f1)
{
    float d = x0 - x1;
    bool  P = (t != 0);
    float w = P ? 0.85f : 0.15f;

    float a2 = P ? fmaf(K2F, d, c1) : fmaf(-K2F, d, C0F);
    float nl = lg2f(1.0f + ex2f(a2));
    lsum = fmaf(w, nl, lsum);

    float one = 1.0f - x1;
    float la  = P ? x1 : one;
    float om  = P ? one : x1;
    float lg  = lg2f(la + 1e-9f);
    float sl  = (om * om) * lg;
    fsum = fmaf(w, sl, fsum);

    int s = (__float_as_int(d) >> 31) | 1;     // d<0 -> -1 else +1
    if (P) { S1 += l1 * s; f1 = f1 ? f1 : s; l1 = s; }
    else   { S0 += l0 * s; f0 = f0 ? f0 : s; l0 = s; }
}

__global__ void __launch_bounds__(NTHR, BPSM) fused_loss(
    const float* __restrict__ x, const int* __restrict__ tg,
    float* __restrict__ out, int B, int rpw, float c1)
{
    const int lane = threadIdx.x & 31;
    const int warp = threadIdx.x >> 5;
    const int tid  = threadIdx.x;

    long long wbase = ((long long)blockIdx.x * NWARP + warp) * (long long)rpw;

    float lsum = 0.f, fsum = 0.f;
    int n1 = 0;
    Chain wacc = {0, 0, 0, 0, 0, 0};

    const int iters = rpw >> 8;                 // 256 rows per warp-iteration

    if (wbase + (long long)rpw <= (long long)B) {
        // ---- full path: double-buffered prefetch, no bounds checks ----
        const float4* px = (const float4*)x  + ((wbase + lane * 8) >> 1);
        const int4*   pt = (const int4*)tg + ((wbase + lane * 8) >> 2);

        float4 xa, xb, xc, xd, ya, yb, yc, yd;
        int4   ta, tb, ua, ub;

        auto loadA = [&]() {
            xa = __ldcs(px + 0); xb = __ldcs(px + 1);
            xc = __ldcs(px + 2); xd = __ldcs(px + 3);
            ta = __ldcs(pt + 0); tb = __ldcs(pt + 1);
            asm volatile("prefetch.global.L2 [%0];" :: "l"(px + PFD * 128));
            asm volatile("prefetch.global.L2 [%0];" :: "l"(pt + PFD * 64));
            px += 128; pt += 64;
        };
        auto loadB = [&]() {
            ya = __ldcs(px + 0); yb = __ldcs(px + 1);
            yc = __ldcs(px + 2); yd = __ldcs(px + 3);
            ua = __ldcs(pt + 0); ub = __ldcs(pt + 1);
            asm volatile("prefetch.global.L2 [%0];" :: "l"(px + PFD * 128));
            asm volatile("prefetch.global.L2 [%0];" :: "l"(pt + PFD * 64));
            px += 128; pt += 64;
        };
        auto body = [&](const float4& a, const float4& b, const float4& c,
                        const float4& d2, const int4& t1v, const int4& t2v) {
            int l0 = 0, l1 = 0, S0 = 0, S1 = 0, f0 = 0, f1 = 0;
            row_op(a.x,  a.y,  t1v.x, c1, lsum, fsum, l0, l1, S0, S1, f0, f1);
            row_op(a.z,  a.w,  t1v.y, c1, lsum, fsum, l0, l1, S0, S1, f0, f1);
            row_op(b.x,  b.y,  t1v.z, c1, lsum, fsum, l0, l1, S0, S1, f0, f1);
            row_op(b.z,  b.w,  t1v.w, c1, lsum, fsum, l0, l1, S0, S1, f0, f1);
            row_op(c.x,  c.y,  t2v.x, c1, lsum, fsum, l0, l1, S0, S1, f0, f1);
            row_op(c.z,  c.w,  t2v.y, c1, lsum, fsum, l0, l1, S0, S1, f0, f1);
            row_op(d2.x, d2.y, t2v.z, c1, lsum, fsum, l0, l1, S0, S1, f0, f1);
            row_op(d2.z, d2.w, t2v.w, c1, lsum, fsum, l0, l1, S0, S1, f0, f1);
            n1 += (t1v.x + t1v.y + t1v.z) + (t1v.w + t2v.x + t2v.y) + (t2v.z + t2v.w);
            int F0, L0, Sw0, F1, L1, Sw1;
            warp_chain(f0, l0, S0, lane, F0, L0, Sw0);
            warp_chain(f1, l1, S1, lane, F1, L1, Sw1);
            wacc.S0 += Sw0 + wacc.l0 * F0;
            wacc.f0  = wacc.f0 ? wacc.f0 : F0;
            wacc.l0  = L0 ? L0 : wacc.l0;
            wacc.S1 += Sw1 + wacc.l1 * F1;
            wacc.f1  = wacc.f1 ? wacc.f1 : F1;
            wacc.l1  = L1 ? L1 : wacc.l1;
        };

        loadA();
        int j = 0;
        for (; j + 2 < iters; j += 2) {
            loadB();                       // prefetch j+1 while computing j
            body(xa, xb, xc, xd, ta, tb);
            loadA();                       // prefetch j+2 while computing j+1
            body(ya, yb, yc, yd, ua, ub);
        }
        if (iters - j == 2) {
            loadB();
            body(xa, xb, xc, xd, ta, tb);
            body(ya, yb, yc, yd, ua, ub);
        } else {
            body(xa, xb, xc, xd, ta, tb);
        }
    } else if (wbase < (long long)B) {
        // -------- tail path (at most one warp strip crosses B) --------
        for (int j = 0; j < iters; ++j) {
            long long base = wbase + (long long)j * 256;
            if (base >= (long long)B) break;
            long long row0 = base + lane * 8;
            int l0 = 0, l1 = 0, S0 = 0, S1 = 0, f0 = 0, f1 = 0;
            for (int k = 0; k < 8; ++k) {
                long long r = row0 + k;
                if (r < (long long)B) {
                    int t = tg[(int)r];
                    row_op(x[2 * r], x[2 * r + 1], t, c1,
                           lsum, fsum, l0, l1, S0, S1, f0, f1);
                    n1 += t;
                }
            }
            int F0, L0, Sw0, F1, L1, Sw1;
            warp_chain(f0, l0, S0, lane, F0, L0, Sw0);
            warp_chain(f1, l1, S1, lane, F1, L1, Sw1);
            wacc.S0 += Sw0 + wacc.l0 * F0;
            wacc.f0  = wacc.f0 ? wacc.f0 : F0;
            wacc.l0  = L0 ? L0 : wacc.l0;
            wacc.S1 += Sw1 + wacc.l1 * F1;
            wacc.f1  = wacc.f1 ? wacc.f1 : F1;
            wacc.l1  = L1 ? L1 : wacc.l1;
        }
    }

    #pragma unroll
    for (int off = 16; off; off >>= 1) {
        lsum += __shfl_down_sync(0xffffffffu, lsum, off);
        fsum += __shfl_down_sync(0xffffffffu, fsum, off);
    }
    n1 = __reduce_add_sync(0xffffffffu, n1);

    __shared__ Chain smon[NWARP];
    __shared__ float sls[NWARP], sfs[NWARP];
    __shared__ int   sn1[NWARP];
    if (lane == 0) { smon[warp] = wacc; sls[warp] = lsum; sfs[warp] = fsum; sn1[warp] = n1; }
    __syncthreads();
    if (tid == 0) {
        Chain c = smon[0];
        float fl = sls[0], ff = sfs[0];
        int nn = sn1[0];
        for (int w = 1; w < NWARP; ++w) {
            c = chain_combine(c, smon[w]);
            fl += sls[w]; ff += sfs[w]; nn += sn1[w];
        }
        g_l[blockIdx.x]  = fl;
        g_f[blockIdx.x]  = ff;
        g_n1[blockIdx.x] = nn;
        int* m = g_c[blockIdx.x];
        m[0] = c.f0; m[1] = c.l0; m[2] = c.S0;
        m[3] = c.f1; m[4] = c.l1; m[5] = c.S1;
    }

    // ---- last-block final reduction ----
    __shared__ unsigned s_last;
    if (tid == 0) {
        __threadfence();
        unsigned r = atomicAdd(&g_count, 1u);
        s_last = (r == (unsigned)(gridDim.x - 1));
    }
    __syncthreads();
    if (!s_last) return;
    __threadfence();

    const int CH = (GRID + NTHR - 1) / NTHR;
    Chain c = {0, 0, 0, 0, 0, 0};
    double dl = 0.0, df = 0.0;
    long long nn = 0;
    #pragma unroll
    for (int k = 0; k < CH; ++k) {
        int i = tid * CH + k;
        if (i < GRID) {
            const int* m = g_c[i];
            Chain b = {m[0], m[1], m[2], m[3], m[4], m[5]};
            c = chain_combine(c, b);
            dl += (double)g_l[i]; df += (double)g_f[i]; nn += g_n1[i];
        }
    }
    int F0, L0, S0, F1, L1, S1;
    warp_chain(c.f0, c.l0, c.S0, lane, F0, L0, S0);
    warp_chain(c.f1, c.l1, c.S1, lane, F1, L1, S1);
    #pragma unroll
    for (int off = 16; off; off >>= 1) {
        dl += __shfl_down_sync(0xffffffffu, dl, off);
        df += __shfl_down_sync(0xffffffffu, df, off);
        nn += __shfl_down_sync(0xffffffffu, nn, off);
    }

    __shared__ Chain s2mon[NWARP];
    __shared__ double s2l[NWARP], s2f[NWARP];
    __shared__ long long s2n[NWARP];
    if (lane == 0) {
        Chain wc = {F0, L0, S0, F1, L1, S1};
        s2mon[warp] = wc; s2l[warp] = dl; s2f[warp] = df; s2n[warp] = nn;
    }
    __syncthreads();
    if (tid == 0) {
        Chain t = s2mon[0];
        double tl = s2l[0], tf = s2f[0];
        long long tn = s2n[0];
        for (int w = 1; w < NWARP; ++w) {
            t = chain_combine(t, s2mon[w]);
            tl += s2l[w]; tf += s2f[w]; tn += s2n[w];
        }
        long long n1t = tn;
        long long n0t = (long long)B - n1t;
        double W     = 0.15 * (double)n0t + 0.85 * (double)n1t;
        double ldam  = LN2D * tl / W;
        double focal = -LN2D * tf / (double)B;
        double p0 = (n0t > 0) ? (double)t.S0 / (double)n0t : 0.0;
        double p1 = (n1t > 0) ? (double)t.S1 / (double)n1t : 0.0;
        double dp = p0 - p1;
        out[0] = (float)(ldam + focal + dp * dp);
        __threadfence();
        g_count = 0;
    }
}

extern "C" void kernel_launch(void* const* d_in, const int* in_sizes, int n_in,
                              void* d_out, int out_size)
{
    const float* x  = (const float*)d_in[0];
    const int*   tg = (const int*)d_in[1];
    int B = in_sizes[1];

    // rows per warp, multiple of 256 (one warp-iteration)
    int wtot = GRID * NWARP;
    int rpw = (B + wtot - 1) / wtot;
    rpw = (rpw + 255) & ~255;

    // class-1 LDAM margin * 30 * log2(e)
    float c1 = (float)(30.0 * 0.5 * pow(85.0 / 900.0, 0.25) * 1.4426950408889634);

    fused_loss<<<GRID, NTHR>>>(x, tg, (float*)d_out, B, rpw, c1);
}

// round 14
// speedup vs baseline: 1.4143x; 1.0589x over previous
#include <cuda_runtime.h>
#include <math.h>

#define BPSM  3              // blocks per SM -> 84-reg budget, room for double buffer
#define GRID  (148 * BPSM)   // one wave
#define NTHR  256
#define NWARP (NTHR / 32)
#define PFD   4              // prefetch distance in 256-row iterations

#define K2F   43.28085122666891f    // 30*log2(e)
#define C0F   21.640425613334455f   // 15*log2(e)
#define LN2D  0.6931471805599453

__device__ __forceinline__ float ex2f(float x){ float r; asm("ex2.approx.ftz.f32 %0, %1;" : "=f"(r) : "f"(x)); return r; }
__device__ __forceinline__ float lg2f(float x){ float r; asm("lg2.approx.ftz.f32 %0, %1;" : "=f"(r) : "f"(x)); return r; }

struct Chain { int f0, l0, S0, f1, l1, S1; };

__device__ __forceinline__ Chain chain_combine(const Chain& a, const Chain& b) {
    Chain r;
    r.S0 = a.S0 + b.S0 + a.l0 * b.f0;
    r.S1 = a.S1 + b.S1 + a.l1 * b.f1;
    r.f0 = a.f0 ? a.f0 : b.f0;
    r.f1 = a.f1 ? a.f1 : b.f1;
    r.l0 = b.l0 ? b.l0 : a.l0;
    r.l1 = b.l1 ? b.l1 : a.l1;
    return r;
}

// Ballot+shfl ordered combine of 32 lane-chains (one class) in O(1).
__device__ __forceinline__ void warp_chain(int f, int l, int S, int lane,
                                           int& Fw, int& Lw, int& Sw)
{
    unsigned m     = __ballot_sync(0xffffffffu, f != 0);
    unsigned below = m & ((1u << lane) - 1u);
    int prev_l = __shfl_sync(0xffffffffu, l, below ? (31 - __clz(below)) : 0);
    int term   = (f != 0 && below) ? prev_l * f : 0;
    Sw = __reduce_add_sync(0xffffffffu, S + term);
    int fsrc = m ? (__ffs(m) - 1) : 0;
    int lsrc = m ? (31 - __clz(m)) : 0;
    Fw = __shfl_sync(0xffffffffu, f, fsrc);
    Lw = __shfl_sync(0xffffffffu, l, lsrc);
    if (!m) { Fw = 0; Lw = 0; }
}

__device__ float    g_l[GRID];
__device__ float    g_f[GRID];
__device__ int      g_n1[GRID];
__device__ int      g_c[GRID][6];
__device__ unsigned g_count = 0;   // reset by last block each run (replay-safe)

// Per-row work, log2 domain, weights folded into the accumulators.
__device__ __forceinline__ void row_op(float x0, float x1, int t, float c1,
                                       float& lsum, float& fsum,
                                       int& l0, int& l1, int& S0, int& S1,
                                       int& f0, int& f1)
{
    float d = x0 - x1;
    bool  P = (t != 0);

    float a2 = P ? fmaf(K2F, d, c1) : fmaf(-K2F, d, C0F);
    float nl = lg2f(1.0f + ex2f(a2));
    if (P) lsum = fmaf(0.85f, nl, lsum); else lsum = fmaf(0.15f, nl, lsum);

    float one = 1.0f - x1;
    float la  = P ? x1 : one;
    float om  = P ? one : x1;
    float lg  = lg2f(la + 1e-9f);
    float sl  = (om * om) * lg;
    if (P) fsum = fmaf(0.85f, sl, fsum); else fsum = fmaf(0.15f, sl, fsum);

    int s = (__float_as_int(d) >> 31) | 1;     // d<0 -> -1 else +1
    if (P) { S1 += l1 * s; f1 = f1 ? f1 : s; l1 = s; }
    else   { S0 += l0 * s; f0 = f0 ? f0 : s; l0 = s; }
}

__global__ void __launch_bounds__(NTHR, BPSM) fused_loss(
    const float* __restrict__ x, const int* __restrict__ tg,
    float* __restrict__ out, int B, int rpw, float c1)
{
    const int lane = threadIdx.x & 31;
    const int warp = threadIdx.x >> 5;
    const int tid  = threadIdx.x;

    long long wbase = ((long long)blockIdx.x * NWARP + warp) * (long long)rpw;

    float lsum = 0.f, fsum = 0.f;
    int n1 = 0;
    Chain wacc = {0, 0, 0, 0, 0, 0};

    const int iters = rpw >> 8;                 // 256 rows per iteration

    if (wbase + (long long)rpw <= (long long)B) {
        // ---- full path: double-buffered prefetch, no bounds checks ----
        const float4* px = (const float4*)x  + ((wbase + lane * 8) >> 1);
        const int4*   pt = (const int4*)tg + ((wbase + lane * 8) >> 2);

        float4 xa, xb, xc, xd, ya, yb, yc, yd;
        int4   ta, tb, ua, ub;

        auto loadA = [&]() {
            xa = __ldcs(px + 0); xb = __ldcs(px + 1);
            xc = __ldcs(px + 2); xd = __ldcs(px + 3);
            ta = __ldcs(pt + 0); tb = __ldcs(pt + 1);
            // L2 prefetch PFD iterations ahead (covers the lines this warp
            // will consume then; invalid addresses are silently ignored)
            asm volatile("prefetch.global.L2 [%0];" :: "l"(px + PFD * 128));
            asm volatile("prefetch.global.L2 [%0];" :: "l"(pt + PFD * 64));
            px += 128; pt += 64;
        };
        auto loadB = [&]() {
            ya = __ldcs(px + 0); yb = __ldcs(px + 1);
            yc = __ldcs(px + 2); yd = __ldcs(px + 3);
            ua = __ldcs(pt + 0); ub = __ldcs(pt + 1);
            asm volatile("prefetch.global.L2 [%0];" :: "l"(px + PFD * 128));
            asm volatile("prefetch.global.L2 [%0];" :: "l"(pt + PFD * 64));
            px += 128; pt += 64;
        };
        auto body = [&](const float4& a, const float4& b, const float4& c,
                        const float4& d2, const int4& t1v, const int4& t2v) {
            int l0 = 0, l1 = 0, S0 = 0, S1 = 0, f0 = 0, f1 = 0;
            row_op(a.x,  a.y,  t1v.x, c1, lsum, fsum, l0, l1, S0, S1, f0, f1);
            row_op(a.z,  a.w,  t1v.y, c1, lsum, fsum, l0, l1, S0, S1, f0, f1);
            row_op(b.x,  b.y,  t1v.z, c1, lsum, fsum, l0, l1, S0, S1, f0, f1);
            row_op(b.z,  b.w,  t1v.w, c1, lsum, fsum, l0, l1, S0, S1, f0, f1);
            row_op(c.x,  c.y,  t2v.x, c1, lsum, fsum, l0, l1, S0, S1, f0, f1);
            row_op(c.z,  c.w,  t2v.y, c1, lsum, fsum, l0, l1, S0, S1, f0, f1);
            row_op(d2.x, d2.y, t2v.z, c1, lsum, fsum, l0, l1, S0, S1, f0, f1);
            row_op(d2.z, d2.w, t2v.w, c1, lsum, fsum, l0, l1, S0, S1, f0, f1);
            n1 += (t1v.x + t1v.y + t1v.z) + (t1v.w + t2v.x + t2v.y) + (t2v.z + t2v.w);
            int F0, L0, Sw0, F1, L1, Sw1;
            warp_chain(f0, l0, S0, lane, F0, L0, Sw0);
            warp_chain(f1, l1, S1, lane, F1, L1, Sw1);
            wacc.S0 += Sw0 + wacc.l0 * F0;
            wacc.f0  = wacc.f0 ? wacc.f0 : F0;
            wacc.l0  = L0 ? L0 : wacc.l0;
            wacc.S1 += Sw1 + wacc.l1 * F1;
            wacc.f1  = wacc.f1 ? wacc.f1 : F1;
            wacc.l1  = L1 ? L1 : wacc.l1;
        };

        loadA();
        int j = 0;
        for (; j + 2 < iters; j += 2) {
            loadB();                       // prefetch j+1 while computing j
            body(xa, xb, xc, xd, ta, tb);
            loadA();                       // prefetch j+2 while computing j+1
            body(ya, yb, yc, yd, ua, ub);
        }
        if (iters - j == 2) {
            loadB();
            body(xa, xb, xc, xd, ta, tb);
            body(ya, yb, yc, yd, ua, ub);
        } else {
            body(xa, xb, xc, xd, ta, tb);
        }
    } else if (wbase < (long long)B) {
        // -------- tail path (at most one warp strip crosses B) --------
        for (int j = 0; j < iters; ++j) {
            long long base = wbase + (long long)j * 256;
            if (base >= (long long)B) break;
            long long row0 = base + lane * 8;
            int l0 = 0, l1 = 0, S0 = 0, S1 = 0, f0 = 0, f1 = 0;
            for (int k = 0; k < 8; ++k) {
                long long r = row0 + k;
                if (r < (long long)B) {
                    int t = tg[(int)r];
                    row_op(x[2 * r], x[2 * r + 1], t, c1,
                           lsum, fsum, l0, l1, S0, S1, f0, f1);
                    n1 += t;
                }
            }
            int F0, L0, Sw0, F1, L1, Sw1;
            warp_chain(f0, l0, S0, lane, F0, L0, Sw0);
            warp_chain(f1, l1, S1, lane, F1, L1, Sw1);
            wacc.S0 += Sw0 + wacc.l0 * F0;
            wacc.f0  = wacc.f0 ? wacc.f0 : F0;
            wacc.l0  = L0 ? L0 : wacc.l0;
            wacc.S1 += Sw1 + wacc.l1 * F1;
            wacc.f1  = wacc.f1 ? wacc.f1 : F1;
            wacc.l1  = L1 ? L1 : wacc.l1;
        }
    }

    #pragma unroll
    for (int off = 16; off; off >>= 1) {
        lsum += __shfl_down_sync(0xffffffffu, lsum, off);
        fsum += __shfl_down_sync(0xffffffffu, fsum, off);
    }
    n1 = __reduce_add_sync(0xffffffffu, n1);

    __shared__ Chain smon[NWARP];
    __shared__ float sls[NWARP], sfs[NWARP];
    __shared__ int   sn1[NWARP];
    if (lane == 0) { smon[warp] = wacc; sls[warp] = lsum; sfs[warp] = fsum; sn1[warp] = n1; }
    __syncthreads();
    if (tid == 0) {
        Chain c = smon[0];
        float fl = sls[0], ff = sfs[0];
        int nn = sn1[0];
        for (int w = 1; w < NWARP; ++w) {
            c = chain_combine(c, smon[w]);
            fl += sls[w]; ff += sfs[w]; nn += sn1[w];
        }
        g_l[blockIdx.x]  = fl;
        g_f[blockIdx.x]  = ff;
        g_n1[blockIdx.x] = nn;
        int* m = g_c[blockIdx.x];
        m[0] = c.f0; m[1] = c.l0; m[2] = c.S0;
        m[3] = c.f1; m[4] = c.l1; m[5] = c.S1;
    }

    // ---- last-block final reduction ----
    __shared__ unsigned s_last;
    if (tid == 0) {
        __threadfence();
        unsigned r = atomicAdd(&g_count, 1u);
        s_last = (r == (unsigned)(gridDim.x - 1));
    }
    __syncthreads();
    if (!s_last) return;
    __threadfence();

    const int CH = (GRID + NTHR - 1) / NTHR;
    Chain c = {0, 0, 0, 0, 0, 0};
    double dl = 0.0, df = 0.0;
    long long nn = 0;
    #pragma unroll
    for (int k = 0; k < CH; ++k) {
        int i = tid * CH + k;
        if (i < GRID) {
            const int* m = g_c[i];
            Chain b = {m[0], m[1], m[2], m[3], m[4], m[5]};
            c = chain_combine(c, b);
            dl += (double)g_l[i]; df += (double)g_f[i]; nn += g_n1[i];
        }
    }
    int F0, L0, S0, F1, L1, S1;
    warp_chain(c.f0, c.l0, c.S0, lane, F0, L0, S0);
    warp_chain(c.f1, c.l1, c.S1, lane, F1, L1, S1);
    #pragma unroll
    for (int off = 16; off; off >>= 1) {
        dl += __shfl_down_sync(0xffffffffu, dl, off);
        df += __shfl_down_sync(0xffffffffu, df, off);
        nn += __shfl_down_sync(0xffffffffu, nn, off);
    }

    __shared__ Chain s2mon[NWARP];
    __shared__ double s2l[NWARP], s2f[NWARP];
    __shared__ long long s2n[NWARP];
    if (lane == 0) {
        Chain wc = {F0, L0, S0, F1, L1, S1};
        s2mon[warp] = wc; s2l[warp] = dl; s2f[warp] = df; s2n[warp] = nn;
    }
    __syncthreads();
    if (tid == 0) {
        Chain t = s2mon[0];
        double tl = s2l[0], tf = s2f[0];
        long long tn = s2n[0];
        for (int w = 1; w < NWARP; ++w) {
            t = chain_combine(t, s2mon[w]);
            tl += s2l[w]; tf += s2f[w]; tn += s2n[w];
        }
        long long n1t = tn;
        long long n0t = (long long)B - n1t;
        double W     = 0.15 * (double)n0t + 0.85 * (double)n1t;
        double ldam  = LN2D * tl / W;
        double focal = -LN2D * tf / (double)B;
        double p0 = (n0t > 0) ? (double)t.S0 / (double)n0t : 0.0;
        double p1 = (n1t > 0) ? (double)t.S1 / (double)n1t : 0.0;
        double dp = p0 - p1;
        out[0] = (float)(ldam + focal + dp * dp);
        __threadfence();
        g_count = 0;
    }
}

extern "C" void kernel_launch(void* const* d_in, const int* in_sizes, int n_in,
                              void* d_out, int out_size)
{
    const float* x  = (const float*)d_in[0];
    const int*   tg = (const int*)d_in[1];
    int B = in_sizes[1];

    // rows per warp, multiple of 256 (one iteration)
    int wtot = GRID * NWARP;
    int rpw = (B + wtot - 1) / wtot;
    rpw = (rpw + 255) & ~255;

    // class-1 LDAM margin * 30 * log2(e)
    float c1 = (float)(30.0 * 0.5 * pow(85.0 / 900.0, 0.25) * 1.4426950408889634);

    fused_loss<<<GRID, NTHR>>>(x, tg, (float*)d_out, B, rpw, c1);
}